// round 5
// baseline (speedup 1.0000x reference)
#include <cuda_runtime.h>
#include <cstddef>

// Problem constants
#define N_    32
#define C_    64      // CIN == COUT
#define T_    1024
#define V_    25
#define K_    3
#define O_    192     // K_*COUT
#define EPSV  1e-5f

#define TPOS  4                    // t positions per block in pass 1
#define NBLK1 (N_ * (T_ / TPOS))   // 8192 blocks

// ---- smem layout (floats) for k_gcn ----
// xs  [4][64][28]   : 7168   (reused as ags[64][101] after compute)
// Af  [3][25][28]   : 2100
// Ws  [192][65]     : 12480  (Ws[(k*64+cin)*65 + c] = W[(k*64+c)*64+cin])
// be  [64][25]      : 1600
// cs  [3][25]       : 75
// part[512]         : 512
#define XS_OFF   0
#define AF_OFF   7168
#define WS_OFF   9268
#define BE_OFF   21748
#define CS_OFF   23348
#define PART_OFF 23423
#define SMEM_FLOATS 23935
#define SMEM_BYTES (SMEM_FLOATS * 4)

// ---- device scratch (no allocations allowed; __device__ globals are the sanctioned path) ----
__device__ float g_agg[(size_t)N_ * C_ * T_ * V_];   // 200 MiB pre-BN activations
__device__ float g_psum[NBLK1 * C_];
__device__ float g_psumsq[NBLK1 * C_];
__device__ float g_scale[C_];
__device__ float g_shift[C_];

// ============================================================================
// Pass 1: fused 1x1-conv + multi-subset graph aggregation + partial BN stats
// ============================================================================
__global__ __launch_bounds__(256, 2)
void k_gcn(const float* __restrict__ x, const float* __restrict__ W,
           const float* __restrict__ b, const float* __restrict__ A,
           const float* __restrict__ PA)
{
    extern __shared__ float sm[];
    float* xs   = sm + XS_OFF;    // [p][cin][28]
    float* Af   = sm + AF_OFF;    // [(k*25+v)][28]
    float* Ws   = sm + WS_OFF;    // [(k*64+cin)][65]
    float* be   = sm + BE_OFF;    // [c][25]
    float* cs   = sm + CS_OFF;    // [k][25]
    float* part = sm + PART_OFF;  // [512]

    const int tid = threadIdx.x;
    const int bi  = blockIdx.x;
    const int n   = bi >> 8;            // 256 t-tiles per n
    const int t0  = (bi & 255) * TPOS;

    // Load W (coalesced reads), write transposed with pad-65 (conflict-free).
    for (int i = tid; i < O_ * C_; i += 256) {
        int o = i >> 6, cin = i & 63;          // W[o][cin]
        int k = o >> 6, c = o & 63;            // o = k*64 + c
        Ws[(k * 64 + cin) * 65 + c] = W[i];
    }
    // Afull = A + PA, rows padded to 28 for float4 reads.
    for (int i = tid; i < K_ * V_ * V_; i += 256) {
        int kv = i / 25, w = i % 25;
        Af[kv * 28 + w] = A[i] + PA[i];
    }
    // x tile: per cin, 100 contiguous floats (t0..t0+3, v=0..24) -> coalesced.
    const float* xb = x + (size_t)n * (C_ * T_ * V_) + (size_t)t0 * V_;
    for (int i = tid; i < 6400; i += 256) {
        int cin = i / 100, r = i % 100;
        int p = r / 25, v = r % 25;
        xs[(p * 64 + cin) * 28 + v] = xb[(size_t)cin * (T_ * V_) + r];
    }
    __syncthreads();

    // colsum[k][w] = sum_v Af[k][v][w]
    if (tid < 75) {
        int k = tid / 25, w = tid % 25;
        float s = 0.f;
        #pragma unroll
        for (int v = 0; v < 25; v++) s += Af[(k * 25 + v) * 28 + w];
        cs[tid] = s;
    }
    __syncthreads();

    // beff[c][w] = sum_k b[k*64+c] * colsum[k][w]
    for (int i = tid; i < C_ * V_; i += 256) {
        int c = i / 25, w = i % 25;
        float s = 0.f;
        #pragma unroll
        for (int k = 0; k < 3; k++) s += __ldg(&b[k * 64 + c]) * cs[k * 25 + w];
        be[i] = s;
    }
    __syncthreads();

    // ---- main compute: thread owns (c, p) ----
    const int c = tid & 63;
    const int p = tid >> 6;

    float agg[25];
    #pragma unroll
    for (int w = 0; w < 25; w++) agg[w] = be[c * 25 + w];

    const float* xp = xs + p * 64 * 28;

    for (int k = 0; k < 3; k++) {
        float y[25];
        #pragma unroll
        for (int v = 0; v < 25; v++) y[v] = 0.f;

        const float* Wk = Ws + (k * 64) * 65 + c;
        #pragma unroll 4
        for (int cin = 0; cin < 64; cin++) {
            float wv = Wk[cin * 65];                      // conflict-free (lanes = consecutive c)
            const float4* xr = (const float4*)(xp + cin * 28);  // broadcast across warp
            #pragma unroll
            for (int q = 0; q < 6; q++) {
                float4 xv = xr[q];
                y[4*q+0] += wv * xv.x; y[4*q+1] += wv * xv.y;
                y[4*q+2] += wv * xv.z; y[4*q+3] += wv * xv.w;
            }
            y[24] += wv * xp[cin * 28 + 24];
        }

        #pragma unroll 5
        for (int v = 0; v < 25; v++) {
            float yv = y[v];
            const float4* ar = (const float4*)(Af + (k * 25 + v) * 28); // broadcast
            #pragma unroll
            for (int q = 0; q < 6; q++) {
                float4 av = ar[q];
                agg[4*q+0] += yv * av.x; agg[4*q+1] += yv * av.y;
                agg[4*q+2] += yv * av.z; agg[4*q+3] += yv * av.w;
            }
            agg[24] += yv * Af[(k * 25 + v) * 28 + 24];
        }
    }

    // per-thread stats
    float s1 = 0.f, s2 = 0.f;
    #pragma unroll
    for (int w = 0; w < 25; w++) { float a = agg[w]; s1 += a; s2 += a * a; }

    // stage agg into smem (reuse xs region; stride 101 -> conflict-free), then
    // coalesced gmem store (avoids 32-sector scattered STG).
    __syncthreads();                     // everyone done reading xs
    float* ags = sm + XS_OFF;            // [c][101], uses 6464 <= 7168 floats
    #pragma unroll
    for (int w = 0; w < 25; w++) ags[c * 101 + p * 25 + w] = agg[w];
    part[tid] = s1; part[256 + tid] = s2;
    __syncthreads();

    float* ob = g_agg + ((size_t)(n * 64) * T_ + t0) * V_;
    for (int i = tid; i < 6400; i += 256) {
        int cc = i / 100, r = i % 100;
        ob[(size_t)cc * (T_ * V_) + r] = ags[cc * 101 + r];
    }

    if (tid < 64) {   // deterministic 4-way reduce per channel
        float p1 = part[tid] + part[64 + tid] + part[128 + tid] + part[192 + tid];
        float p2 = part[256 + tid] + part[320 + tid] + part[384 + tid] + part[448 + tid];
        g_psum[bi * 64 + tid]   = p1;
        g_psumsq[bi * 64 + tid] = p2;
    }
}

// ============================================================================
// Pass 2: reduce partials -> per-channel scale/shift
// ============================================================================
__global__ void k_stats(const float* __restrict__ gamma, const float* __restrict__ beta)
{
    const int ch = blockIdx.x;
    const int tid = threadIdx.x;
    __shared__ float s1s[256], s2s[256];
    float s1 = 0.f, s2 = 0.f;
    for (int j = tid; j < NBLK1; j += 256) {
        s1 += g_psum[j * 64 + ch];
        s2 += g_psumsq[j * 64 + ch];
    }
    s1s[tid] = s1; s2s[tid] = s2;
    __syncthreads();
    for (int st = 128; st > 0; st >>= 1) {
        if (tid < st) { s1s[tid] += s1s[tid + st]; s2s[tid] += s2s[tid + st]; }
        __syncthreads();
    }
    if (tid == 0) {
        const float cnt = (float)N_ * T_ * V_;        // biased batch stats
        float mu   = s1s[0] / cnt;
        float var  = s2s[0] / cnt - mu * mu;
        float rstd = rsqrtf(var + EPSV);
        float sc   = gamma[ch] * rstd;
        g_scale[ch] = sc;
        g_shift[ch] = beta[ch] - mu * sc;
    }
}

// ============================================================================
// Pass 3: out = relu(agg*scale + shift + x), float4 (25600 % 4 == 0 per (n,c))
// ============================================================================
__global__ __launch_bounds__(256)
void k_out(const float* __restrict__ x, float* __restrict__ out)
{
    const int total4 = (N_ * C_ * T_ * V_) / 4;   // 13,107,200
    int i = blockIdx.x * blockDim.x + threadIdx.x;
    if (i >= total4) return;
    const float4* x4 = (const float4*)x;
    const float4* a4 = (const float4*)g_agg;
    float4* o4 = (float4*)out;

    int c = (i / 6400) & 63;                      // 6400 float4 per (n,c) plane
    float sc = g_scale[c], sh = g_shift[c];
    float4 a = a4[i], xv = x4[i];
    float4 r;
    r.x = fmaxf(fmaf(a.x, sc, sh) + xv.x, 0.f);
    r.y = fmaxf(fmaf(a.y, sc, sh) + xv.y, 0.f);
    r.z = fmaxf(fmaf(a.z, sc, sh) + xv.z, 0.f);
    r.w = fmaxf(fmaf(a.w, sc, sh) + xv.w, 0.f);
    o4[i] = r;
}

// ============================================================================
extern "C" void kernel_launch(void* const* d_in, const int* in_sizes, int n_in,
                              void* d_out, int out_size)
{
    const float* x     = (const float*)d_in[0];
    const float* W     = (const float*)d_in[1];
    const float* b     = (const float*)d_in[2];
    const float* A     = (const float*)d_in[3];
    const float* PA    = (const float*)d_in[4];
    const float* gamma = (const float*)d_in[5];
    const float* beta  = (const float*)d_in[6];
    float* out = (float*)d_out;

    // idempotent; needed for >48KB dynamic smem
    cudaFuncSetAttribute(k_gcn, cudaFuncAttributeMaxDynamicSharedMemorySize, SMEM_BYTES);

    k_gcn<<<NBLK1, 256, SMEM_BYTES>>>(x, W, b, A, PA);
    k_stats<<<C_, 256>>>(gamma, beta);
    const int total4 = (N_ * C_ * T_ * V_) / 4;
    k_out<<<(total4 + 255) / 256, 256>>>(x, out);
}

// round 7
// speedup vs baseline: 1.1281x; 1.1281x over previous
#include <cuda_runtime.h>
#include <cstddef>

// Problem constants
#define N_    32
#define C_    64      // CIN == COUT
#define T_    1024
#define V_    25
#define K_    3
#define O_    192     // K_*COUT
#define EPSV  1e-5f

#define TPOS  4                    // t positions per block in pass 1
#define NBLK1 (N_ * (T_ / TPOS))   // 8192 blocks

// ---- smem layout (floats) for k_gcn ----
#define XS_OFF   0        // xs  [4][64][28] : 7168 (reused as ags[64][101])
#define AF_OFF   7168     // Af  [3][25][28] : 2100
#define WS_OFF   9268     // Ws  [192][65]   : 12480
#define BE_OFF   21748    // be  [64][25]    : 1600
#define CS_OFF   23348    // cs  [3][25]     : 75
#define PART_OFF 23424    // part[512]  (16B aligned)
#define SMEM_FLOATS 23936
#define SMEM_BYTES (SMEM_FLOATS * 4)

// ---- device scratch ----
__device__ float g_agg[(size_t)N_ * C_ * T_ * V_];   // 200 MiB pre-BN activations
__device__ float g_psum[NBLK1 * C_];
__device__ float g_psumsq[NBLK1 * C_];
__device__ float g_scale[C_];
__device__ float g_shift[C_];

// ---- packed fp32x2 helpers (Blackwell FFMA2 — only reachable via PTX) ----
__device__ __forceinline__ unsigned long long pack2(float a, float b) {
    unsigned long long r;
    asm("mov.b64 %0, {%1, %2};" : "=l"(r) : "f"(a), "f"(b));
    return r;
}
__device__ __forceinline__ void unpack2(unsigned long long p, float& a, float& b) {
    asm("mov.b64 {%0, %1}, %2;" : "=f"(a), "=f"(b) : "l"(p));
}
__device__ __forceinline__ unsigned long long fma2(unsigned long long a,
                                                   unsigned long long b,
                                                   unsigned long long c) {
    unsigned long long d;
    asm("fma.rn.f32x2 %0, %1, %2, %3;" : "=l"(d) : "l"(a), "l"(b), "l"(c));
    return d;
}

// ============================================================================
// Pass 1: fused 1x1-conv + multi-subset graph aggregation + partial BN stats
// ============================================================================
__global__ __launch_bounds__(256, 2)
void k_gcn(const float* __restrict__ x, const float* __restrict__ W,
           const float* __restrict__ b, const float* __restrict__ A,
           const float* __restrict__ PA)
{
    extern __shared__ float sm[];
    float* xs   = sm + XS_OFF;    // [p][cin][28]
    float* Af   = sm + AF_OFF;    // [(k*25+v)][28]
    float* Ws   = sm + WS_OFF;    // [(k*64+cin)][65]
    float* be   = sm + BE_OFF;    // [c][25]
    float* cs   = sm + CS_OFF;    // [k][25]
    float* part = sm + PART_OFF;  // [512]

    const int tid = threadIdx.x;
    const int bi  = blockIdx.x;
    const int n   = bi >> 8;            // 256 t-tiles per n
    const int t0  = (bi & 255) * TPOS;

    // W transposed with pad-65 (conflict-free stores: consecutive cin, stride 65).
    for (int i = tid; i < O_ * C_; i += 256) {
        int o = i >> 6, cin = i & 63;          // W[o][cin]
        int k = o >> 6, c = o & 63;            // o = k*64 + c
        Ws[(k * 64 + cin) * 65 + c] = W[i];
    }
    // Afull = A + PA, rows padded to 28 (112B -> 16B aligned rows).
    for (int i = tid; i < K_ * V_ * V_; i += 256) {
        int kv = i / 25, w = i % 25;
        Af[kv * 28 + w] = A[i] + PA[i];
    }
    // x tile: per cin, 100 contiguous floats -> coalesced gmem reads.
    const float* xb = x + (size_t)n * (C_ * T_ * V_) + (size_t)t0 * V_;
    for (int i = tid; i < 6400; i += 256) {
        int cin = i / 100, r = i % 100;
        int p = r / 25, v = r % 25;
        xs[(p * 64 + cin) * 28 + v] = xb[(size_t)cin * (T_ * V_) + r];
    }
    __syncthreads();

    // colsum[k][w] = sum_v Af[k][v][w]
    if (tid < 75) {
        int k = tid / 25, w = tid % 25;
        float s = 0.f;
        #pragma unroll
        for (int v = 0; v < 25; v++) s += Af[(k * 25 + v) * 28 + w];
        cs[tid] = s;
    }
    __syncthreads();

    // beff[c][w] = sum_k b[k*64+c] * colsum[k][w]
    for (int i = tid; i < C_ * V_; i += 256) {
        int c = i / 25, w = i % 25;
        float s = 0.f;
        #pragma unroll
        for (int k = 0; k < 3; k++) s += __ldg(&b[k * 64 + c]) * cs[k * 25 + w];
        be[i] = s;
    }
    __syncthreads();

    // ---- main compute: thread owns (c, p); all FMAs packed f32x2 ----
    const int c = tid & 63;
    const int p = tid >> 6;

    unsigned long long agg2[12];           // agg[0..23] as 12 packed pairs
    float agg24;
    {
        const float* bc = be + c * 25;     // stride-25 scalar reads: conflict-free
        #pragma unroll
        for (int i = 0; i < 12; i++) agg2[i] = pack2(bc[2 * i], bc[2 * i + 1]);
        agg24 = bc[24];
    }

    const float* xp = xs + p * 64 * 28;

    for (int k = 0; k < 3; k++) {
        unsigned long long y2[12];         // y2[i] holds y[2i], y[2i+1]
        float y24 = 0.f;
        #pragma unroll
        for (int i = 0; i < 12; i++) y2[i] = pack2(0.f, 0.f);

        const float* Wk = Ws + (k * 64) * 65 + c;
        #pragma unroll 4
        for (int cin = 0; cin < 64; cin++) {
            float wv = Wk[cin * 65];                         // lanes=consecutive c: conflict-free
            unsigned long long wp = pack2(wv, wv);
            const ulonglong2* xr = (const ulonglong2*)(xp + cin * 28);  // warp-broadcast LDS.128
            // xr[q] covers floats [4q..4q+3] -> packed pairs 2q, 2q+1
            #pragma unroll
            for (int q = 0; q < 6; q++) {
                ulonglong2 xa = xr[q];
                y2[2*q+0] = fma2(wp, xa.x, y2[2*q+0]);
                y2[2*q+1] = fma2(wp, xa.y, y2[2*q+1]);
            }
            y24 = fmaf(wv, xp[cin * 28 + 24], y24);
        }

        // unpack y once, then aggregation stage (packed)
        float ys[25];
        #pragma unroll
        for (int i = 0; i < 12; i++) unpack2(y2[i], ys[2 * i], ys[2 * i + 1]);
        ys[24] = y24;

        #pragma unroll 5
        for (int v = 0; v < 25; v++) {
            float yv = ys[v];
            unsigned long long yp = pack2(yv, yv);
            const ulonglong2* ar = (const ulonglong2*)(Af + (k * 25 + v) * 28); // broadcast
            #pragma unroll
            for (int q = 0; q < 6; q++) {
                ulonglong2 aa = ar[q];
                agg2[2*q+0] = fma2(yp, aa.x, agg2[2*q+0]);
                agg2[2*q+1] = fma2(yp, aa.y, agg2[2*q+1]);
            }
            agg24 = fmaf(yv, Af[(k * 25 + v) * 28 + 24], agg24);
        }
    }

    // unpack agg, per-thread stats
    float aggv[25];
    #pragma unroll
    for (int i = 0; i < 12; i++) unpack2(agg2[i], aggv[2 * i], aggv[2 * i + 1]);
    aggv[24] = agg24;

    float s1 = 0.f, s2 = 0.f;
    #pragma unroll
    for (int w = 0; w < 25; w++) { float a = aggv[w]; s1 += a; s2 += a * a; }

    // stage agg into smem (stride 101 -> conflict-free), then coalesced STG
    __syncthreads();                     // everyone done reading xs
    float* ags = sm + XS_OFF;            // [c][101]
    #pragma unroll
    for (int w = 0; w < 25; w++) ags[c * 101 + p * 25 + w] = aggv[w];
    part[tid] = s1; part[256 + tid] = s2;
    __syncthreads();

    float* ob = g_agg + ((size_t)(n * 64) * T_ + t0) * V_;
    for (int i = tid; i < 6400; i += 256) {
        int cc = i / 100, r = i % 100;
        ob[(size_t)cc * (T_ * V_) + r] = ags[cc * 101 + r];
    }

    if (tid < 64) {   // deterministic 4-way reduce per channel
        float p1 = part[tid] + part[64 + tid] + part[128 + tid] + part[192 + tid];
        float p2 = part[256 + tid] + part[320 + tid] + part[384 + tid] + part[448 + tid];
        g_psum[bi * 64 + tid]   = p1;
        g_psumsq[bi * 64 + tid] = p2;
    }
}

// ============================================================================
// Pass 2: reduce partials -> per-channel scale/shift
// ============================================================================
__global__ void k_stats(const float* __restrict__ gamma, const float* __restrict__ beta)
{
    const int ch = blockIdx.x;
    const int tid = threadIdx.x;
    __shared__ float s1s[256], s2s[256];
    float s1 = 0.f, s2 = 0.f;
    for (int j = tid; j < NBLK1; j += 256) {
        s1 += g_psum[j * 64 + ch];
        s2 += g_psumsq[j * 64 + ch];
    }
    s1s[tid] = s1; s2s[tid] = s2;
    __syncthreads();
    for (int st = 128; st > 0; st >>= 1) {
        if (tid < st) { s1s[tid] += s1s[tid + st]; s2s[tid] += s2s[tid + st]; }
        __syncthreads();
    }
    if (tid == 0) {
        const float cnt = (float)N_ * T_ * V_;        // biased batch stats
        float mu   = s1s[0] / cnt;
        float var  = s2s[0] / cnt - mu * mu;
        float rstd = rsqrtf(var + EPSV);
        float sc   = gamma[ch] * rstd;
        g_scale[ch] = sc;
        g_shift[ch] = beta[ch] - mu * sc;
    }
}

// ============================================================================
// Pass 3: out = relu(agg*scale + shift + x), float4
// ============================================================================
__global__ __launch_bounds__(256)
void k_out(const float* __restrict__ x, float* __restrict__ out)
{
    const int total4 = (N_ * C_ * T_ * V_) / 4;   // 13,107,200
    int i = blockIdx.x * blockDim.x + threadIdx.x;
    if (i >= total4) return;
    const float4* x4 = (const float4*)x;
    const float4* a4 = (const float4*)g_agg;
    float4* o4 = (float4*)out;

    int c = (i / 6400) & 63;                      // 6400 float4 per (n,c) plane
    float sc = g_scale[c], sh = g_shift[c];
    float4 a = a4[i], xv = x4[i];
    float4 r;
    r.x = fmaxf(fmaf(a.x, sc, sh) + xv.x, 0.f);
    r.y = fmaxf(fmaf(a.y, sc, sh) + xv.y, 0.f);
    r.z = fmaxf(fmaf(a.z, sc, sh) + xv.z, 0.f);
    r.w = fmaxf(fmaf(a.w, sc, sh) + xv.w, 0.f);
    o4[i] = r;
}

// ============================================================================
extern "C" void kernel_launch(void* const* d_in, const int* in_sizes, int n_in,
                              void* d_out, int out_size)
{
    const float* x     = (const float*)d_in[0];
    const float* W     = (const float*)d_in[1];
    const float* b     = (const float*)d_in[2];
    const float* A     = (const float*)d_in[3];
    const float* PA    = (const float*)d_in[4];
    const float* gamma = (const float*)d_in[5];
    const float* beta  = (const float*)d_in[6];
    float* out = (float*)d_out;

    cudaFuncSetAttribute(k_gcn, cudaFuncAttributeMaxDynamicSharedMemorySize, SMEM_BYTES);

    k_gcn<<<NBLK1, 256, SMEM_BYTES>>>(x, W, b, A, PA);
    k_stats<<<C_, 256>>>(gamma, beta);
    const int total4 = (N_ * C_ * T_ * V_) / 4;
    k_out<<<(total4 + 255) / 256, 256>>>(x, out);
}

// round 8
// speedup vs baseline: 1.3261x; 1.1755x over previous
#include <cuda_runtime.h>
#include <cstddef>

// Problem constants
#define N_    32
#define C_    64      // CIN == COUT
#define T_    1024
#define V_    25
#define K_    3
#define O_    192     // K_*COUT
#define EPSV  1e-5f

#define TPOS  4                    // t positions per block in pass 1
#define NBLK1 (N_ * (T_ / TPOS))   // 8192 blocks

// ---- smem layout (floats) for k_gcn ----
#define XS_OFF   0        // xs  [4][64][28] : 7168 (reused as ags[64][101])
#define AF_OFF   7168     // Af  [3][25][28] : 2100
#define WS_OFF   9268     // Ws2 [3][64][68] : 13056  (Ws2[k][c][cin])
#define BE_OFF   22324    // be  [64][25]    : 1600
#define CS_OFF   23924    // cs  [3][25]     : 76
#define PART_OFF 24000    // part[512]
#define SMEM_FLOATS 24512
#define SMEM_BYTES (SMEM_FLOATS * 4)

// ---- device scratch ----
__device__ float g_agg[(size_t)N_ * C_ * T_ * V_];   // 200 MiB pre-BN activations
__device__ float g_psum[NBLK1 * C_];
__device__ float g_psumsq[NBLK1 * C_];
__device__ float g_scale[C_];
__device__ float g_shift[C_];

// ---- packed fp32x2 helpers (Blackwell FFMA2 via PTX) ----
__device__ __forceinline__ unsigned long long pack2(float a, float b) {
    unsigned long long r;
    asm("mov.b64 %0, {%1, %2};" : "=l"(r) : "f"(a), "f"(b));
    return r;
}
__device__ __forceinline__ void unpack2(unsigned long long p, float& a, float& b) {
    asm("mov.b64 {%0, %1}, %2;" : "=f"(a), "=f"(b) : "l"(p));
}
__device__ __forceinline__ unsigned long long fma2(unsigned long long a,
                                                   unsigned long long b,
                                                   unsigned long long c) {
    unsigned long long d;
    asm("fma.rn.f32x2 %0, %1, %2, %3;" : "=l"(d) : "l"(a), "l"(b), "l"(c));
    return d;
}

// ============================================================================
// Pass 1: fused 1x1-conv + multi-subset graph aggregation + partial BN stats
// ============================================================================
__global__ __launch_bounds__(256, 2)
void k_gcn(const float* __restrict__ x, const float* __restrict__ W,
           const float* __restrict__ b, const float* __restrict__ A,
           const float* __restrict__ PA)
{
    extern __shared__ float sm[];
    float* xs   = sm + XS_OFF;    // [p][cin][28]
    float* Af   = sm + AF_OFF;    // [(k*25+v)][28]
    float* Ws2  = sm + WS_OFF;    // [k][c][68] = W[(k*64+c)*64 + cin]
    float* be   = sm + BE_OFF;    // [c][25]
    float* cs   = sm + CS_OFF;    // [k][25]
    float* part = sm + PART_OFF;  // [512]

    const int tid = threadIdx.x;
    const int bi  = blockIdx.x;
    const int n   = bi >> 8;            // 256 t-tiles per n
    const int t0  = (bi & 255) * TPOS;

    // W -> Ws2[k][c][cin], row pad 68 (float4 reads over cin are conflict-free).
    for (int i = tid; i < O_ * C_; i += 256) {
        int o = i >> 6, cin = i & 63;          // W[o][cin]
        int k = o >> 6, c = o & 63;
        Ws2[k * (64 * 68) + c * 68 + cin] = W[i];
    }
    // Afull = A + PA, rows padded to 28 (16B aligned rows).
    for (int i = tid; i < K_ * V_ * V_; i += 256) {
        int kv = i / 25, w = i % 25;
        Af[kv * 28 + w] = A[i] + PA[i];
    }
    // x tile: per cin, 100 contiguous floats -> coalesced gmem reads.
    const float* xb = x + (size_t)n * (C_ * T_ * V_) + (size_t)t0 * V_;
    for (int i = tid; i < 6400; i += 256) {
        int cin = i / 100, r = i % 100;
        int p = r / 25, v = r % 25;
        xs[(p * 64 + cin) * 28 + v] = xb[(size_t)cin * (T_ * V_) + r];
    }
    __syncthreads();

    // colsum[k][w] = sum_v Af[k][v][w]
    if (tid < 75) {
        int k = tid / 25, w = tid % 25;
        float s = 0.f;
        #pragma unroll
        for (int v = 0; v < 25; v++) s += Af[(k * 25 + v) * 28 + w];
        cs[tid] = s;
    }
    __syncthreads();

    // beff[c][w] = sum_k b[k*64+c] * colsum[k][w]
    for (int i = tid; i < C_ * V_; i += 256) {
        int c = i / 25, w = i % 25;
        float s = 0.f;
        #pragma unroll
        for (int k = 0; k < 3; k++) s += __ldg(&b[k * 64 + c]) * cs[k * 25 + w];
        be[i] = s;
    }
    __syncthreads();

    // ---- main compute: thread owns (c, p) ----
    const int c = tid & 63;
    const int p = tid >> 6;

    const float* xp  = xs + p * 64 * 28;
    const float* Wc  = Ws2 + c * 68;          // k-stride 64*68=4352

    // Three y accumulator sets (one per k), packed f32x2. x loaded ONCE per cin.
    unsigned long long ya[12], yb[12], yc[12];
    float y24a = 0.f, y24b = 0.f, y24c = 0.f;
    #pragma unroll
    for (int i = 0; i < 12; i++) { ya[i] = 0ull; yb[i] = 0ull; yc[i] = 0ull; }

    #pragma unroll 2
    for (int c4 = 0; c4 < 16; c4++) {
        // 3 conflict-free LDS.128: weights for 4 consecutive cin, all 3 k
        float4 w0 = *(const float4*)(Wc + c4 * 4);
        float4 w1 = *(const float4*)(Wc + 4352 + c4 * 4);
        float4 w2 = *(const float4*)(Wc + 8704 + c4 * 4);
        float w0a[4] = {w0.x, w0.y, w0.z, w0.w};
        float w1a[4] = {w1.x, w1.y, w1.z, w1.w};
        float w2a[4] = {w2.x, w2.y, w2.z, w2.w};

        #pragma unroll
        for (int j = 0; j < 4; j++) {
            const int cin = c4 * 4 + j;
            const ulonglong2* xr = (const ulonglong2*)(xp + cin * 28); // broadcast
            unsigned long long wp0 = pack2(w0a[j], w0a[j]);
            unsigned long long wp1 = pack2(w1a[j], w1a[j]);
            unsigned long long wp2 = pack2(w2a[j], w2a[j]);
            #pragma unroll
            for (int q = 0; q < 6; q++) {
                ulonglong2 xv = xr[q];
                ya[2*q+0] = fma2(wp0, xv.x, ya[2*q+0]);
                ya[2*q+1] = fma2(wp0, xv.y, ya[2*q+1]);
                yb[2*q+0] = fma2(wp1, xv.x, yb[2*q+0]);
                yb[2*q+1] = fma2(wp1, xv.y, yb[2*q+1]);
                yc[2*q+0] = fma2(wp2, xv.x, yc[2*q+0]);
                yc[2*q+1] = fma2(wp2, xv.y, yc[2*q+1]);
            }
            float x24 = xp[cin * 28 + 24];                 // broadcast scalar
            y24a = fmaf(w0a[j], x24, y24a);
            y24b = fmaf(w1a[j], x24, y24b);
            y24c = fmaf(w2a[j], x24, y24c);
        }
    }

    // ---- aggregation: agg[w] += y_k[v] * Af[k][v][w], consume one k at a time ----
    unsigned long long agg2[12];
    float agg24;
    {
        const float* bc = be + c * 25;        // conflict-free scalar reads
        #pragma unroll
        for (int i = 0; i < 12; i++) agg2[i] = pack2(bc[2 * i], bc[2 * i + 1]);
        agg24 = bc[24];
    }

#define AGG_ONE_V(kk, vv, yval)                                            \
    {                                                                      \
        float yv_ = (yval);                                                \
        unsigned long long yp_ = pack2(yv_, yv_);                          \
        const ulonglong2* ar_ = (const ulonglong2*)(Af + ((kk)*25+(vv))*28);\
        _Pragma("unroll")                                                  \
        for (int q_ = 0; q_ < 6; q_++) {                                   \
            ulonglong2 aa_ = ar_[q_];                                      \
            agg2[2*q_+0] = fma2(yp_, aa_.x, agg2[2*q_+0]);                 \
            agg2[2*q_+1] = fma2(yp_, aa_.y, agg2[2*q_+1]);                 \
        }                                                                  \
        agg24 = fmaf(yv_, Af[((kk)*25+(vv))*28 + 24], agg24);              \
    }

#define AGG_K(kk, YARR, Y24)                                               \
    {                                                                      \
        _Pragma("unroll")                                                  \
        for (int i_ = 0; i_ < 12; i_++) {                                  \
            float va_, vb_;                                                \
            unpack2(YARR[i_], va_, vb_);                                   \
            AGG_ONE_V(kk, 2*i_,   va_);                                    \
            AGG_ONE_V(kk, 2*i_+1, vb_);                                    \
        }                                                                  \
        AGG_ONE_V(kk, 24, Y24);                                            \
    }

    AGG_K(0, ya, y24a);
    AGG_K(1, yb, y24b);
    AGG_K(2, yc, y24c);

    // unpack agg, per-thread stats
    float aggv[25];
    #pragma unroll
    for (int i = 0; i < 12; i++) unpack2(agg2[i], aggv[2 * i], aggv[2 * i + 1]);
    aggv[24] = agg24;

    float s1 = 0.f, s2 = 0.f;
    #pragma unroll
    for (int w = 0; w < 25; w++) { float a = aggv[w]; s1 += a; s2 += a * a; }

    // stage agg into smem (stride 101 -> conflict-free), then coalesced STG
    __syncthreads();                     // everyone done reading xs
    float* ags = sm + XS_OFF;            // [c][101]
    #pragma unroll
    for (int w = 0; w < 25; w++) ags[c * 101 + p * 25 + w] = aggv[w];
    part[tid] = s1; part[256 + tid] = s2;
    __syncthreads();

    float* ob = g_agg + ((size_t)(n * 64) * T_ + t0) * V_;
    for (int i = tid; i < 6400; i += 256) {
        int cc = i / 100, r = i % 100;
        ob[(size_t)cc * (T_ * V_) + r] = ags[cc * 101 + r];
    }

    if (tid < 64) {   // deterministic 4-way reduce per channel
        float p1 = part[tid] + part[64 + tid] + part[128 + tid] + part[192 + tid];
        float p2 = part[256 + tid] + part[320 + tid] + part[384 + tid] + part[448 + tid];
        g_psum[bi * 64 + tid]   = p1;
        g_psumsq[bi * 64 + tid] = p2;
    }
}

// ============================================================================
// Pass 2: reduce partials -> per-channel scale/shift
// ============================================================================
__global__ void k_stats(const float* __restrict__ gamma, const float* __restrict__ beta)
{
    const int ch = blockIdx.x;
    const int tid = threadIdx.x;
    __shared__ float s1s[256], s2s[256];
    float s1 = 0.f, s2 = 0.f;
    for (int j = tid; j < NBLK1; j += 256) {
        s1 += g_psum[j * 64 + ch];
        s2 += g_psumsq[j * 64 + ch];
    }
    s1s[tid] = s1; s2s[tid] = s2;
    __syncthreads();
    for (int st = 128; st > 0; st >>= 1) {
        if (tid < st) { s1s[tid] += s1s[tid + st]; s2s[tid] += s2s[tid + st]; }
        __syncthreads();
    }
    if (tid == 0) {
        const float cnt = (float)N_ * T_ * V_;        // biased batch stats
        float mu   = s1s[0] / cnt;
        float var  = s2s[0] / cnt - mu * mu;
        float rstd = rsqrtf(var + EPSV);
        float sc   = gamma[ch] * rstd;
        g_scale[ch] = sc;
        g_shift[ch] = beta[ch] - mu * sc;
    }
}

// ============================================================================
// Pass 3: out = relu(agg*scale + shift + x), float4
// ============================================================================
__global__ __launch_bounds__(256)
void k_out(const float* __restrict__ x, float* __restrict__ out)
{
    const int total4 = (N_ * C_ * T_ * V_) / 4;   // 13,107,200
    int i = blockIdx.x * blockDim.x + threadIdx.x;
    if (i >= total4) return;
    const float4* x4 = (const float4*)x;
    const float4* a4 = (const float4*)g_agg;
    float4* o4 = (float4*)out;

    int c = (i / 6400) & 63;                      // 6400 float4 per (n,c) plane
    float sc = g_scale[c], sh = g_shift[c];
    float4 a = a4[i], xv = x4[i];
    float4 r;
    r.x = fmaxf(fmaf(a.x, sc, sh) + xv.x, 0.f);
    r.y = fmaxf(fmaf(a.y, sc, sh) + xv.y, 0.f);
    r.z = fmaxf(fmaf(a.z, sc, sh) + xv.z, 0.f);
    r.w = fmaxf(fmaf(a.w, sc, sh) + xv.w, 0.f);
    o4[i] = r;
}

// ============================================================================
extern "C" void kernel_launch(void* const* d_in, const int* in_sizes, int n_in,
                              void* d_out, int out_size)
{
    const float* x     = (const float*)d_in[0];
    const float* W     = (const float*)d_in[1];
    const float* b     = (const float*)d_in[2];
    const float* A     = (const float*)d_in[3];
    const float* PA    = (const float*)d_in[4];
    const float* gamma = (const float*)d_in[5];
    const float* beta  = (const float*)d_in[6];
    float* out = (float*)d_out;

    cudaFuncSetAttribute(k_gcn, cudaFuncAttributeMaxDynamicSharedMemorySize, SMEM_BYTES);

    k_gcn<<<NBLK1, 256, SMEM_BYTES>>>(x, W, b, A, PA);
    k_stats<<<C_, 256>>>(gamma, beta);
    const int total4 = (N_ * C_ * T_ * V_) / 4;
    k_out<<<(total4 + 255) / 256, 256>>>(x, out);
}